// round 17
// baseline (speedup 1.0000x reference)
#include <cuda_runtime.h>
#include <cuda.h>
#include <cstdint>

#define NTPL 10
#define NACC 11                                   // 10 cross + 1 x·x
#define PIX 784
#define IMG_BYTES 3136                            // PIX*4
#define TILE 128                                  // images per tile
#define NGRP 4                                    // 4 groups of 32 images
#define CHUNKS 196
#define SCH 28                                    // chunks per stage
#define NSTG 7                                    // stages per tile
#define NBUF 3                                    // smem buffers
#define NWC 15                                    // compute warps (warp 15 = producer)
#define THREADS 512
#define SROW 464                                  // padded stage row: 116w == 4*odd mod 32 -> conflict-free
#define BOX0 116                                  // floats per TMA row (112 used + 4 pad, OOB zero)
#define BUF_BYTES (TILE * SROW)                   // 59392 (128B-aligned stride)
#define TM_OFF (NBUF * BUF_BYTES)                 // 178176 templates [k][chunk] 16B
#define MB_OFF (TM_OFF + NTPL * PIX * 4)          // 209536: full[3] @ +0, consumed[3] @ +48
#define TSQ_OFF (MB_OFF + 96)                     // 10 doubles
#define SMEM_TOTAL (TSQ_OFF + 96)                 // 209728 <= 232448

// Epilogue scratch overlays buffers 0..1 (all consumed, producer parked)
#define RED_OFF 0                                 // 11*15*128*4 = 84480
#define XXD_OFF (NACC * NWC * TILE * 4)           // 84480: 128 doubles
#define DF_OFF (XXD_OFF + TILE * 8)               // 85504: 10*128 floats -> 90624 < 118784

#define FMA2(acc, a, b) \
    asm("fma.rn.f32x2 %0, %1, %2, %0;" : "+l"(acc) : "l"(a), "l"(b))

#define XLOAD(g, OFF) \
    asm("ld.shared.v2.u64 {%0, %1}, [%2+" OFF "];" \
        : "=l"(x01[g]), "=l"(x23[g]) : "r"(xb))

#define KSTEP(k, OFF) do { \
    uint64_t a01, a23; \
    asm("ld.shared.v2.u64 {%0, %1}, [%2+" OFF "];" \
        : "=l"(a01), "=l"(a23) : "r"(tb)); \
    FMA2(acc[k][0], x01[0], a01); FMA2(acc[k][0], x23[0], a23); \
    FMA2(acc[k][1], x01[1], a01); FMA2(acc[k][1], x23[1], a23); \
    FMA2(acc[k][2], x01[2], a01); FMA2(acc[k][2], x23[2], a23); \
    FMA2(acc[k][3], x01[3], a01); FMA2(acc[k][3], x23[3], a23); \
} while (0)

// x group offsets: 32 images * 464B = 14848
#define CHUNK_BODY do { \
    uint64_t x01[NGRP], x23[NGRP]; \
    XLOAD(0, "0"); XLOAD(1, "14848"); XLOAD(2, "29696"); XLOAD(3, "44544"); \
    KSTEP(0, "0");     KSTEP(1, "3136");  KSTEP(2, "6272"); \
    KSTEP(3, "9408");  KSTEP(4, "12544"); KSTEP(5, "15680"); \
    KSTEP(6, "18816"); KSTEP(7, "21952"); KSTEP(8, "25088"); \
    KSTEP(9, "28224"); \
    FMA2(acc[NTPL][0], x01[0], x01[0]); FMA2(acc[NTPL][0], x23[0], x23[0]); \
    FMA2(acc[NTPL][1], x01[1], x01[1]); FMA2(acc[NTPL][1], x23[1], x23[1]); \
    FMA2(acc[NTPL][2], x01[2], x01[2]); FMA2(acc[NTPL][2], x23[2], x23[2]); \
    FMA2(acc[NTPL][3], x01[3], x01[3]); FMA2(acc[NTPL][3], x23[3], x23[3]); \
} while (0)

__device__ __forceinline__ void mbar_wait(uint32_t addr, uint32_t phase) {
    uint32_t done = 0;
    while (!done) {
        asm volatile(
            "{\n\t.reg .pred p;\n\t"
            "mbarrier.try_wait.parity.acquire.cta.shared::cta.b64 p, [%1], %2, 0x989680;\n\t"
            "selp.b32 %0, 1, 0, p;\n\t}"
            : "=r"(done) : "r"(addr), "r"(phase) : "memory");
    }
}

__global__ void __launch_bounds__(THREADS, 1)
mse_argmin_kernel(const __grid_constant__ CUtensorMap tmap,
                  const float* __restrict__ tg, float* __restrict__ out, int ntiles) {
    extern __shared__ float sm[];
    const uint32_t smb = (uint32_t)__cvta_generic_to_shared(sm);
    const int tid = threadIdx.x;
    const int w = tid >> 5;
    const int lane = tid & 31;
    const int G = gridDim.x;
    const int t0 = blockIdx.x;
    const double INV784 = 1.0 / 784.0;

    if (tid == 0) {
        asm volatile("prefetch.tensormap [%0];" :: "l"(&tmap));
        #pragma unroll
        for (int b = 0; b < NBUF; b++) {
            asm volatile("mbarrier.init.shared.b64 [%0], 1;"     // full: TMA tx
                         :: "r"(smb + MB_OFF + (uint32_t)(b * 16)) : "memory");
            asm volatile("mbarrier.init.shared.b64 [%0], %1;"    // consumed: 15 warps
                         :: "r"(smb + MB_OFF + 48u + (uint32_t)(b * 16)), "r"(NWC) : "memory");
        }
        asm volatile("fence.proxy.async;" ::: "memory");
    }
    __syncthreads();

    // Templates -> smem [k][chunk] 16B granules.
    {
        const float4* tg4 = (const float4*)tg;
        float4* tm4 = (float4*)(sm + (TM_OFF >> 2));
        for (int i = tid; i < NTPL * CHUNKS; i += THREADS) tm4[i] = tg4[i];
    }
    // Exact (fp64) squared template norms (one warp per template).
    double* tsq_d = (double*)((char*)sm + TSQ_OFF);
    if (w < NTPL) {
        const float* tp = tg + w * PIX;
        double a = 0.0;
        for (int p = lane; p < PIX; p += 32) a = fma((double)tp[p], (double)tp[p], a);
        #pragma unroll
        for (int s = 16; s > 0; s >>= 1) a += __shfl_xor_sync(0xffffffffu, a, s);
        if (lane == 0) tsq_d[w] = a;
    }
    __syncthreads();

    int gs = 0;                                    // global stage counter (uniform)

    for (int ti = t0; ti < ntiles; ti += G) {
        if (w == NWC) {
            // ---- producer warp: stream 7 fetches, waiting consumed ----
            if (lane == 0) {
                asm volatile("fence.proxy.async;" ::: "memory");  // republish scratch
                for (int s = 0; s < NSTG; s++) {
                    const int g = gs + s;
                    const int b = g % NBUF;
                    if (g >= NBUF)
                        mbar_wait(smb + MB_OFF + 48u + (uint32_t)(b * 16),
                                  (uint32_t)((g / NBUF) - 1) & 1u);
                    const uint32_t fmb = smb + MB_OFF + (uint32_t)(b * 16);
                    asm volatile("mbarrier.arrive.expect_tx.shared.b64 _, [%0], %1;"
                                 :: "r"(fmb), "r"((uint32_t)BUF_BYTES) : "memory");
                    asm volatile(
                        "cp.async.bulk.tensor.2d.shared::cta.global.tile."
                        "mbarrier::complete_tx::bytes [%0], [%1, {%2, %3}], [%4];"
                        :: "r"(smb + (uint32_t)(b * BUF_BYTES)), "l"(&tmap),
                           "r"(s * (SCH * 4)), "r"(ti * TILE), "r"(fmb) : "memory");
                }
            }
        }

        uint64_t acc[NACC][NGRP];
        #pragma unroll
        for (int k = 0; k < NACC; k++)
            #pragma unroll
            for (int g = 0; g < NGRP; g++) acc[k][g] = 0ull;

        if (w < NWC) {
            // ---- consumer warps: per-warp progress, no block syncs ----
            for (int s = 0; s < NSTG; s++) {
                const int g = gs + s;
                const int b = g % NBUF;
                mbar_wait(smb + MB_OFF + (uint32_t)(b * 16), (uint32_t)(g / NBUF) & 1u);

                // warp w owns chunks c == w (mod 15), increasing c
                int r0 = (w - 13 * s) % 15;
                if (r0 < 0) r0 += 15;
                uint32_t xb = smb + (uint32_t)(b * BUF_BYTES)
                            + (uint32_t)(lane * SROW) + (uint32_t)(r0 * 16);
                uint32_t tb = smb + TM_OFF + (uint32_t)((SCH * s + r0) * 16);
                CHUNK_BODY;
                if (r0 < 13) {                    // second owned chunk r0+15
                    xb += 240u; tb += 240u;
                    CHUNK_BODY;
                }
                if (lane == 0)
                    asm volatile("mbarrier.arrive.shared.b64 _, [%0];"
                                 :: "r"(smb + MB_OFF + 48u + (uint32_t)(b * 16)) : "memory");
            }
        }
        gs += NSTG;
        __syncthreads();                          // tile done; buffers all consumed

        // ---- epilogue in buffers 0..1 (identical arithmetic family) ----
        float* red = (float*)((char*)sm + RED_OFF);            // [k][w][img]
        if (w < NWC) {
            #pragma unroll
            for (int k = 0; k < NACC; k++)
                #pragma unroll
                for (int g = 0; g < NGRP; g++) {
                    uint32_t lo, hi;
                    asm("mov.b64 {%0, %1}, %2;" : "=r"(lo), "=r"(hi) : "l"(acc[k][g]));
                    red[(k * NWC + w) * TILE + g * 32 + lane] =
                        __uint_as_float(lo) + __uint_as_float(hi);
                }
        }
        __syncthreads();

        double* xxd = (double*)((char*)sm + XXD_OFF);          // [img]
        float* df = (float*)((char*)sm + DF_OFF);              // [k][img]

        // Pass A: exact 15-way fold of x·x (k=10) via TwoSum -> fp64.
        if (tid < TILE) {
            const float* rp = red + NTPL * (NWC * TILE) + tid;
            float fs = 0.f, fe = 0.f;
            #pragma unroll
            for (int ww = 0; ww < NWC; ww++) {
                const float v = rp[ww * TILE];
                const float tt = fs + v;
                const float z = tt - fs;
                fe += (fs - (tt - z)) + (v - z);
                fs = tt;
            }
            xxd[tid] = (double)fs + (double)fe;
        }
        __syncthreads();

        // Pass B: fold k=0..9 and form fp32-rounded distances (grid-stride).
        for (int p = tid; p < NTPL * TILE; p += THREADS) {
            const int k = p >> 7, img = p & (TILE - 1);
            const float* rp = red + k * (NWC * TILE) + img;
            float fs = 0.f, fe = 0.f;
            #pragma unroll
            for (int ww = 0; ww < NWC; ww++) {
                const float v = rp[ww * TILE];
                const float tt = fs + v;
                const float z = tt - fs;
                fe += (fs - (tt - z)) + (v - z);
                fs = tt;
            }
            const double c = (double)fs + (double)fe;
            df[p] = (float)((fma(-2.0, c, xxd[img]) + tsq_d[k]) * INV784);
        }
        __syncthreads();

        // argmin (strict <, first index wins ties == jnp.argmin).
        if (tid < TILE) {
            float best = df[tid];
            int bi = 0;
            #pragma unroll
            for (int kk = 1; kk < NTPL; kk++) {
                const float v = df[kk * TILE + tid];
                if (v < best) { best = v; bi = kk; }
            }
            out[(size_t)ti * TILE + tid] = (float)bi;
        }
        __syncthreads();                          // scratch dead before next tile
    }
}

typedef CUresult (*EncodeFn)(CUtensorMap*, CUtensorMapDataType, cuuint32_t, void*,
                             const cuuint64_t*, const cuuint64_t*, const cuuint32_t*,
                             const cuuint32_t*, CUtensorMapInterleave, CUtensorMapSwizzle,
                             CUtensorMapL2promotion, CUtensorMapFloatOOBfill);

extern "C" void kernel_launch(void* const* d_in, const int* in_sizes, int n_in,
                              void* d_out, int out_size) {
    // Robust to input ordering: x is the big one.
    const float* a = (const float*)d_in[0];
    const float* b = (const float*)d_in[1];
    const float* xg;
    const float* tg;
    long nx;
    if (in_sizes[0] >= in_sizes[1]) { xg = a; tg = b; nx = in_sizes[0]; }
    else                            { xg = b; tg = a; nx = in_sizes[1]; }

    const int B = (int)(nx / PIX);
    const int ntiles = B / TILE;   // 262144/128 = 2048, exact

    // Encode the x tensormap: [784 cols x B rows] fp32, box [116 x 128]
    // (4 pad columns per stage, OOB zero-filled, never read).
    static CUtensorMap tmap;       // persists across graph replays
    {
        EncodeFn enc = nullptr;
        cudaDriverEntryPointQueryResult qr = cudaDriverEntryPointSuccess;
        cudaError_t e = cudaGetDriverEntryPointByVersion(
            "cuTensorMapEncodeTiled", (void**)&enc, 12000, cudaEnableDefault, &qr);
        if (e != cudaSuccess || qr != cudaDriverEntryPointSuccess || enc == nullptr) {
            enc = nullptr;
            cudaGetDriverEntryPoint("cuTensorMapEncodeTiled", (void**)&enc,
                                    cudaEnableDefault, &qr);
        }
        if (enc != nullptr) {
            cuuint64_t gdims[2] = {(cuuint64_t)PIX, (cuuint64_t)B};
            cuuint64_t gstride[1] = {(cuuint64_t)IMG_BYTES};
            cuuint32_t box[2] = {(cuuint32_t)BOX0, (cuuint32_t)TILE};
            cuuint32_t estride[2] = {1, 1};
            enc(&tmap, CU_TENSOR_MAP_DATA_TYPE_FLOAT32, 2, (void*)xg,
                gdims, gstride, box, estride,
                CU_TENSOR_MAP_INTERLEAVE_NONE, CU_TENSOR_MAP_SWIZZLE_NONE,
                CU_TENSOR_MAP_L2_PROMOTION_L2_128B, CU_TENSOR_MAP_FLOAT_OOB_FILL_NONE);
        }
    }

    int dev = 0;
    cudaGetDevice(&dev);
    int nsm = 148;
    cudaDeviceGetAttribute(&nsm, cudaDevAttrMultiProcessorCount, dev);
    int grid = nsm < ntiles ? nsm : ntiles;

    cudaFuncSetAttribute(mse_argmin_kernel,
                         cudaFuncAttributeMaxDynamicSharedMemorySize, SMEM_TOTAL);

    mse_argmin_kernel<<<grid, THREADS, SMEM_TOTAL>>>(tmap, tg, (float*)d_out, ntiles);
}